// round 8
// baseline (speedup 1.0000x reference)
#include <cuda_runtime.h>
#include <cuda_fp16.h>
#include <cstdint>

#define MDIM 8192
#define NDIM 11008
#define KDIM 4096
#define BM 128
#define BN 256
#define BK 64
#define NTHREADS 256
#define KTILES (KDIM / BK)          // 64
#define STAGES 3

#define LDS_W 72                    // halfs per smem row (144 B)
#define ROW_B 144
#define A_BYTES (BM * ROW_B)        // 18432
#define B_BYTES (BN * ROW_B)        // 36864
#define STAGE_BYTES (A_BYTES + B_BYTES)   // 55296
#define SMEM_TOTAL (STAGES * STAGE_BYTES) // 165888

static_assert(MDIM % BM == 0 && NDIM % BN == 0 && KDIM % BK == 0, "tiling");

// ---- scratch: fp16 x and pre-dequantized fp16 W ----
__device__ __half g_x[(size_t)MDIM * KDIM];   // 64 MB
__device__ __half g_w[(size_t)NDIM * KDIM];   // 86 MB

__device__ __forceinline__ uint32_t smem_u32(const void* p) {
    return (uint32_t)__cvta_generic_to_shared(p);
}
__device__ __forceinline__ uint32_t h2u(__half2 h) {
    return *reinterpret_cast<uint32_t*>(&h);
}
__device__ __forceinline__ void mma16816(float acc[4],
    uint32_t a0, uint32_t a1, uint32_t a2, uint32_t a3,
    uint32_t b0, uint32_t b1)
{
    asm volatile(
        "mma.sync.aligned.m16n8k16.row.col.f32.f16.f16.f32 "
        "{%0,%1,%2,%3},{%4,%5,%6,%7},{%8,%9},{%0,%1,%2,%3};"
        : "+f"(acc[0]), "+f"(acc[1]), "+f"(acc[2]), "+f"(acc[3])
        : "r"(a0), "r"(a1), "r"(a2), "r"(a3), "r"(b0), "r"(b1));
}
#define CP_ASYNC16(dst, src) \
    asm volatile("cp.async.cg.shared.global [%0], [%1], 16;" :: "r"(dst), "l"(src) : "memory")
#define CP_COMMIT() asm volatile("cp.async.commit_group;" ::: "memory")

// ---- prepass 1: x fp32 -> fp16 (lossless; values are fp16-representable) ----
__global__ void convert_x_kernel(const float* __restrict__ x) {
    size_t i = ((size_t)blockIdx.x * blockDim.x + threadIdx.x) * 4;
    if (i >= (size_t)MDIM * KDIM) return;
    float4 f = *reinterpret_cast<const float4*>(x + i);
    uint2 o;
    o.x = h2u(__floats2half2_rn(f.x, f.y));
    o.y = h2u(__floats2half2_rn(f.z, f.w));
    *reinterpret_cast<uint2*>(g_x + i) = o;
}

// ---- prepass 2: int4 packed -> fp16 dequant, (w-8)*s in fp16 (matches ref) ----
__global__ void dequant_w_kernel(const int* __restrict__ wp,
                                 const float* __restrict__ scales) {
    const size_t idx = (size_t)blockIdx.x * blockDim.x + threadIdx.x;
    if (idx >= (size_t)NDIM * 512) return;          // 512 int4-chunks per row
    const int n  = (int)(idx >> 9);
    const int kq = ((int)idx & 511) * 4;            // packed index within row
    const int grp = kq >> 6;                        // k = 2*kq, group = k/128
    const __half2 s2 = __half2half2(__float2half_rn(scales[n * 32 + grp]));
    const __half2 c1032 = __half2half2(__ushort_as_half(0x6408));   // 1032.0 exact
    int4 v4 = *reinterpret_cast<const int4*>(wp + (size_t)n * 2048 + kq);
    uint32_t v[4] = { (uint32_t)v4.x, (uint32_t)v4.y, (uint32_t)v4.z, (uint32_t)v4.w };
    uint4 o;
    uint32_t q[4];
    #pragma unroll
    for (int e = 0; e < 4; e++) {
        // one byte per int32: low nibble -> even k, high nibble -> odd k
        uint32_t t = (v[e] & 0xFu) | ((v[e] << 12) & 0x000F0000u) | 0x64006400u;
        __half2 hh = *reinterpret_cast<__half2*>(&t);
        hh = __hmul2(__hsub2(hh, c1032), s2);       // (w-8) exact, one rounding on *s
        q[e] = h2u(hh);
    }
    o.x = q[0]; o.y = q[1]; o.z = q[2]; o.w = q[3];
    *reinterpret_cast<uint4*>(g_w + (size_t)n * KDIM + kq * 2) = o;
}

// ---- main GEMM: cp.async 3-stage pipeline, 8 warps of 64x64, mma.sync ----
__global__ void __launch_bounds__(NTHREADS, 1)
w4a16_gemm_kernel(float* __restrict__ out)
{
    extern __shared__ char smem[];
    const int tid = threadIdx.x;
    const int m0 = blockIdx.x * BM;
    const int n0 = blockIdx.y * BN;

    // warp layout: 2 (M) x 4 (N), warp tile 64x64
    const int warp = tid >> 5;
    const int lane = tid & 31;
    const int wm = warp & 1;
    const int wn = warp >> 1;
    const int gid = lane >> 2;
    const int tig = lane & 3;

    // cp.async mapping: A: thread -> row tid>>1, 4 chunks; B: row tid, 8 chunks
    const int arow = tid >> 1;
    const int acol = (tid & 1) * 4;
    const __half* aSrc = g_x + (size_t)(m0 + arow) * KDIM + acol * 8;
    const __half* bSrc = g_w + (size_t)(n0 + tid) * KDIM;

    auto issue_stage = [&](int t) {
        const int s = t % STAGES;
        const int k0 = t * BK;
        const uint32_t aDst = smem_u32(smem) + s * STAGE_BYTES + arow * ROW_B + acol * 16;
        const uint32_t bDst = smem_u32(smem) + s * STAGE_BYTES + A_BYTES + tid * ROW_B;
        #pragma unroll
        for (int j = 0; j < 4; j++) CP_ASYNC16(aDst + j * 16, aSrc + k0 + j * 8);
        #pragma unroll
        for (int j = 0; j < 8; j++) CP_ASYNC16(bDst + j * 16, bSrc + k0 + j * 8);
        CP_COMMIT();
    };

    float acc[4][8][4];
    #pragma unroll
    for (int i = 0; i < 4; i++)
        #pragma unroll
        for (int j = 0; j < 8; j++)
            #pragma unroll
            for (int c = 0; c < 4; c++) acc[i][j][c] = 0.f;

    auto compute_stage = [&](int t) {
        const int s = t % STAGES;
        const __half* A = reinterpret_cast<const __half*>(smem + s * STAGE_BYTES);
        const __half* B = reinterpret_cast<const __half*>(smem + s * STAGE_BYTES + A_BYTES);
        #pragma unroll
        for (int ks = 0; ks < 4; ks++) {
            const int kb = ks * 16 + tig * 2;
            uint32_t bf[8][2];
            #pragma unroll
            for (int nt = 0; nt < 8; nt++) {
                const __half* Bp = B + (wn * 64 + nt * 8 + gid) * LDS_W + kb;
                bf[nt][0] = *reinterpret_cast<const uint32_t*>(Bp);
                bf[nt][1] = *reinterpret_cast<const uint32_t*>(Bp + 8);
            }
            #pragma unroll
            for (int mt = 0; mt < 4; mt++) {
                const __half* Ap = A + (wm * 64 + mt * 16 + gid) * LDS_W + kb;
                uint32_t a0 = *reinterpret_cast<const uint32_t*>(Ap);
                uint32_t a1 = *reinterpret_cast<const uint32_t*>(Ap + 8 * LDS_W);
                uint32_t a2 = *reinterpret_cast<const uint32_t*>(Ap + 8);
                uint32_t a3 = *reinterpret_cast<const uint32_t*>(Ap + 8 * LDS_W + 8);
                #pragma unroll
                for (int nt = 0; nt < 8; nt++)
                    mma16816(acc[mt][nt], a0, a1, a2, a3, bf[nt][0], bf[nt][1]);
            }
        }
    };

    issue_stage(0);
    issue_stage(1);
    for (int t = 0; t < KTILES; t++) {
        if (t == KTILES - 1) asm volatile("cp.async.wait_group 0;" ::: "memory");
        else                 asm volatile("cp.async.wait_group 1;" ::: "memory");
        __syncthreads();
        if (t + 2 < KTILES) issue_stage(t + 2);
        compute_stage(t);
    }

    // epilogue: fp32 acc -> fp16 round (match reference cast) -> fp32 store
    float* outBase = out + (size_t)(m0 + wm * 64) * NDIM + n0 + wn * 64;
    #pragma unroll
    for (int mt = 0; mt < 4; mt++) {
        #pragma unroll
        for (int nt = 0; nt < 8; nt++) {
            float v0 = __half2float(__float2half_rn(acc[mt][nt][0]));
            float v1 = __half2float(__float2half_rn(acc[mt][nt][1]));
            float v2 = __half2float(__float2half_rn(acc[mt][nt][2]));
            float v3 = __half2float(__float2half_rn(acc[mt][nt][3]));
            *reinterpret_cast<float2*>(outBase + (size_t)(mt * 16 + gid) * NDIM + nt * 8 + tig * 2)
                = make_float2(v0, v1);
            *reinterpret_cast<float2*>(outBase + (size_t)(mt * 16 + 8 + gid) * NDIM + nt * 8 + tig * 2)
                = make_float2(v2, v3);
        }
    }
}

extern "C" void kernel_launch(void* const* d_in, const int* in_sizes, int n_in,
                              void* d_out, int out_size) {
    // Dispatch by element count (dtype-independent; fp16 refs arrive as fp32).
    const float* x      = nullptr;   // 8192*4096  fp32
    const int*   wp     = nullptr;   // 11008*2048 int32
    const float* scales = nullptr;   // 11008*32   fp32
    for (int i = 0; i < n_in; i++) {
        if      (in_sizes[i] == 33554432) x      = (const float*)d_in[i];
        else if (in_sizes[i] == 22544384) wp     = (const int*)d_in[i];
        else if (in_sizes[i] == 352256)   scales = (const float*)d_in[i];
    }
    float* out = (float*)d_out;
    if (!x || !wp || !scales) return;

    // prepass 1: x -> fp16  (33.5M elems / 4 per thread)
    convert_x_kernel<<<(MDIM * (size_t)KDIM / 4 + 255) / 256, 256>>>(x);
    // prepass 2: W -> fp16 dequant (11008*512 int4-chunks)
    dequant_w_kernel<<<((size_t)NDIM * 512 + 255) / 256, 256>>>(wp, scales);

    cudaFuncSetAttribute(w4a16_gemm_kernel,
                         cudaFuncAttributeMaxDynamicSharedMemorySize, SMEM_TOTAL);
    dim3 grid(MDIM / BM, NDIM / BN);   // (64, 43)
    w4a16_gemm_kernel<<<grid, NTHREADS, SMEM_TOTAL>>>(out);
}

// round 9
// speedup vs baseline: 1.1686x; 1.1686x over previous
#include <cuda_runtime.h>
#include <cuda_fp16.h>
#include <cstdint>

#define MDIM 8192
#define NDIM 11008
#define KDIM 4096
#define BM 128
#define BN 128
#define BK 64
#define NTHREADS 256
#define KTILES (KDIM / BK)          // 64
#define STAGES 3

#define LDS_W 72                    // halfs per smem row (144 B)
#define ROW_B 144
#define A_BYTES (BM * ROW_B)        // 18432
#define B_BYTES (BN * ROW_B)        // 18432
#define STAGE_BYTES (A_BYTES + B_BYTES)   // 36864
#define SMEM_TOTAL (STAGES * STAGE_BYTES) // 110592

static_assert(MDIM % BM == 0 && NDIM % BN == 0 && KDIM % BK == 0, "tiling");

// ---- scratch: fp16 x and pre-dequantized fp16 W ----
__device__ __half g_x[(size_t)MDIM * KDIM];   // 64 MB
__device__ __half g_w[(size_t)NDIM * KDIM];   // 86 MB

__device__ __forceinline__ uint32_t smem_u32(const void* p) {
    return (uint32_t)__cvta_generic_to_shared(p);
}
__device__ __forceinline__ uint32_t h2u(__half2 h) {
    return *reinterpret_cast<uint32_t*>(&h);
}
__device__ __forceinline__ void mma16816(float acc[4],
    uint32_t a0, uint32_t a1, uint32_t a2, uint32_t a3,
    uint32_t b0, uint32_t b1)
{
    asm volatile(
        "mma.sync.aligned.m16n8k16.row.col.f32.f16.f16.f32 "
        "{%0,%1,%2,%3},{%4,%5,%6,%7},{%8,%9},{%0,%1,%2,%3};"
        : "+f"(acc[0]), "+f"(acc[1]), "+f"(acc[2]), "+f"(acc[3])
        : "r"(a0), "r"(a1), "r"(a2), "r"(a3), "r"(b0), "r"(b1));
}
#define CP_ASYNC16(dst, src) \
    asm volatile("cp.async.cg.shared.global [%0], [%1], 16;" :: "r"(dst), "l"(src) : "memory")
#define CP_COMMIT() asm volatile("cp.async.commit_group;" ::: "memory")

// ---- prepass 1: x fp32 -> fp16 (lossless; values are fp16-representable) ----
__global__ void convert_x_kernel(const float* __restrict__ x) {
    size_t i = ((size_t)blockIdx.x * blockDim.x + threadIdx.x) * 4;
    if (i >= (size_t)MDIM * KDIM) return;
    float4 f = *reinterpret_cast<const float4*>(x + i);
    uint2 o;
    o.x = h2u(__floats2half2_rn(f.x, f.y));
    o.y = h2u(__floats2half2_rn(f.z, f.w));
    *reinterpret_cast<uint2*>(g_x + i) = o;
}

// ---- prepass 2: int4 packed -> fp16 dequant, (w-8)*s in fp16 (matches ref) ----
__global__ void dequant_w_kernel(const int* __restrict__ wp,
                                 const float* __restrict__ scales) {
    const size_t idx = (size_t)blockIdx.x * blockDim.x + threadIdx.x;
    if (idx >= (size_t)NDIM * 512) return;          // 512 int4-chunks per row
    const int n  = (int)(idx >> 9);
    const int kq = ((int)idx & 511) * 4;            // packed index within row
    const int grp = kq >> 6;                        // k = 2*kq, group = k/128
    const __half2 s2 = __half2half2(__float2half_rn(scales[n * 32 + grp]));
    const __half2 c1032 = __half2half2(__ushort_as_half(0x6408));   // 1032.0 exact
    int4 v4 = *reinterpret_cast<const int4*>(wp + (size_t)n * 2048 + kq);
    uint32_t v[4] = { (uint32_t)v4.x, (uint32_t)v4.y, (uint32_t)v4.z, (uint32_t)v4.w };
    uint4 o;
    uint32_t q[4];
    #pragma unroll
    for (int e = 0; e < 4; e++) {
        // one byte per int32: low nibble -> even k, high nibble -> odd k
        uint32_t t = (v[e] & 0xFu) | ((v[e] << 12) & 0x000F0000u) | 0x64006400u;
        __half2 hh = *reinterpret_cast<__half2*>(&t);
        hh = __hmul2(__hsub2(hh, c1032), s2);       // (w-8) exact, one rounding on *s
        q[e] = h2u(hh);
    }
    o.x = q[0]; o.y = q[1]; o.z = q[2]; o.w = q[3];
    *reinterpret_cast<uint4*>(g_w + (size_t)n * KDIM + kq * 2) = o;
}

// ---- main GEMM: cp.async 3-stage, 2 CTAs/SM, 8 warps of 64x32, ldmatrix ----
__global__ void __launch_bounds__(NTHREADS, 2)
w4a16_gemm_kernel(float* __restrict__ out)
{
    extern __shared__ char smem[];
    const uint32_t sb = smem_u32(smem);
    const int tid = threadIdx.x;
    const int m0 = blockIdx.x * BM;
    const int n0 = blockIdx.y * BN;

    // warp layout: 2 (M) x 4 (N), warp tile 64x32
    const int warp = tid >> 5;
    const int lane = tid & 31;
    const int wm = warp & 1;
    const int wn = warp >> 1;
    const int gid = lane >> 2;
    const int tig = lane & 3;

    // cp.async mapping: thread -> row tid>>1, 4 of the 8 16B-chunks per row
    const int prow = tid >> 1;
    const int pcol = (tid & 1) * 4;     // chunk index base
    const __half* aSrc = g_x + (size_t)(m0 + prow) * KDIM + pcol * 8;
    const __half* bSrc = g_w + (size_t)(n0 + prow) * KDIM + pcol * 8;

    auto issue_stage = [&](int t) {
        const int s = t % STAGES;
        const int k0 = t * BK;
        const uint32_t aDst = sb + s * STAGE_BYTES + prow * ROW_B + pcol * 16;
        const uint32_t bDst = aDst + A_BYTES;
        #pragma unroll
        for (int j = 0; j < 4; j++) {
            CP_ASYNC16(aDst + j * 16, aSrc + k0 + j * 8);
            CP_ASYNC16(bDst + j * 16, bSrc + k0 + j * 8);
        }
        CP_COMMIT();
    };

    float acc[4][4][4];
    #pragma unroll
    for (int i = 0; i < 4; i++)
        #pragma unroll
        for (int j = 0; j < 4; j++)
            #pragma unroll
            for (int c = 0; c < 4; c++) acc[i][j][c] = 0.f;

    // ldmatrix lane->address components (verified: R2 ldmatrix == R3 manual)
    const int aRow = wm * 64 + (lane & 15);          // + mt*16
    const int aCol = (lane >> 4) * 8;                // + ks*16
    const int bRow = wn * 32 + (lane & 7) + ((lane >> 4) << 3);  // + p*16
    const int bCol = ((lane >> 3) & 1) * 8;          // + ks*16

    auto compute_stage = [&](int t) {
        const int s = t % STAGES;
        const uint32_t A = sb + s * STAGE_BYTES;
        const uint32_t B = A + A_BYTES;
        #pragma unroll
        for (int ks = 0; ks < 4; ks++) {
            uint32_t a[4][4];
            #pragma unroll
            for (int mt = 0; mt < 4; mt++) {
                const uint32_t addr = A + (aRow + mt * 16) * ROW_B + (aCol + ks * 16) * 2;
                asm volatile("ldmatrix.sync.aligned.m8n8.x4.shared.b16 {%0,%1,%2,%3}, [%4];"
                    : "=r"(a[mt][0]), "=r"(a[mt][1]), "=r"(a[mt][2]), "=r"(a[mt][3])
                    : "r"(addr));
            }
            uint32_t b[4][2];
            #pragma unroll
            for (int p = 0; p < 2; p++) {
                const uint32_t addr = B + (bRow + p * 16) * ROW_B + (bCol + ks * 16) * 2;
                uint32_t r0, r1, r2, r3;
                asm volatile("ldmatrix.sync.aligned.m8n8.x4.shared.b16 {%0,%1,%2,%3}, [%4];"
                    : "=r"(r0), "=r"(r1), "=r"(r2), "=r"(r3) : "r"(addr));
                b[p * 2 + 0][0] = r0; b[p * 2 + 0][1] = r1;
                b[p * 2 + 1][0] = r2; b[p * 2 + 1][1] = r3;
            }
            #pragma unroll
            for (int mt = 0; mt < 4; mt++)
                #pragma unroll
                for (int nt = 0; nt < 4; nt++)
                    mma16816(acc[mt][nt], a[mt][0], a[mt][1], a[mt][2], a[mt][3],
                             b[nt][0], b[nt][1]);
        }
    };

    issue_stage(0);
    issue_stage(1);
    for (int t = 0; t < KTILES; t++) {
        if (t == KTILES - 1) asm volatile("cp.async.wait_group 0;" ::: "memory");
        else                 asm volatile("cp.async.wait_group 1;" ::: "memory");
        __syncthreads();
        if (t + 2 < KTILES) issue_stage(t + 2);
        compute_stage(t);
    }

    // epilogue: fp32 acc -> fp16 round (match reference cast) -> fp32 store
    float* outBase = out + (size_t)(m0 + wm * 64) * NDIM + n0 + wn * 32;
    #pragma unroll
    for (int mt = 0; mt < 4; mt++) {
        #pragma unroll
        for (int nt = 0; nt < 4; nt++) {
            float v0 = __half2float(__float2half_rn(acc[mt][nt][0]));
            float v1 = __half2float(__float2half_rn(acc[mt][nt][1]));
            float v2 = __half2float(__float2half_rn(acc[mt][nt][2]));
            float v3 = __half2float(__float2half_rn(acc[mt][nt][3]));
            *reinterpret_cast<float2*>(outBase + (size_t)(mt * 16 + gid) * NDIM + nt * 8 + tig * 2)
                = make_float2(v0, v1);
            *reinterpret_cast<float2*>(outBase + (size_t)(mt * 16 + 8 + gid) * NDIM + nt * 8 + tig * 2)
                = make_float2(v2, v3);
        }
    }
}

extern "C" void kernel_launch(void* const* d_in, const int* in_sizes, int n_in,
                              void* d_out, int out_size) {
    // Dispatch by element count (dtype-independent; fp16 refs arrive as fp32).
    const float* x      = nullptr;   // 8192*4096  fp32
    const int*   wp     = nullptr;   // 11008*2048 int32
    const float* scales = nullptr;   // 11008*32   fp32
    for (int i = 0; i < n_in; i++) {
        if      (in_sizes[i] == 33554432) x      = (const float*)d_in[i];
        else if (in_sizes[i] == 22544384) wp     = (const int*)d_in[i];
        else if (in_sizes[i] == 352256)   scales = (const float*)d_in[i];
    }
    float* out = (float*)d_out;
    if (!x || !wp || !scales) return;

    convert_x_kernel<<<(MDIM * (size_t)KDIM / 4 + 255) / 256, 256>>>(x);
    dequant_w_kernel<<<((size_t)NDIM * 512 + 255) / 256, 256>>>(wp, scales);

    cudaFuncSetAttribute(w4a16_gemm_kernel,
                         cudaFuncAttributeMaxDynamicSharedMemorySize, SMEM_TOTAL);
    dim3 grid(MDIM / BM, NDIM / BN);   // (64, 86), bm fastest for B-panel L2 reuse
    w4a16_gemm_kernel<<<grid, NTHREADS, SMEM_TOTAL>>>(out);
}